// round 5
// baseline (speedup 1.0000x reference)
#include <cuda_runtime.h>
#include <cuda_bf16.h>
#include <math.h>
#include <stdint.h>

#define DIM   256
#define MAXN  100000
#define MAXE  500000

// ---------------- scratch ---------------------------------------------------
__device__ float g_v[(size_t)MAXN * DIM];     // v[n,:] = W_k @ prev[n,:]
__device__ float g_comb[(size_t)MAXN * DIM];  // unnormalized sum ex * x
__device__ float g_wkT[DIM * DIM];            // W_k transposed
__device__ float g_bq[MAXN];                  // b_k . prev[n]
__device__ float g_denom[MAXN];               // sum ex per node

// ---------------- helpers ---------------------------------------------------
__device__ __forceinline__ void red_add_v4(float* addr, float a, float b, float c, float d) {
    asm volatile("red.global.add.v4.f32 [%0], {%1,%2,%3,%4};"
                 :: "l"(addr), "f"(a), "f"(b), "f"(c), "f"(d) : "memory");
}
__device__ __forceinline__ void cp_async16(uint32_t saddr, const void* gaddr, int bytes) {
    asm volatile("cp.async.ca.shared.global [%0], [%1], 16, %2;\n"
                 :: "r"(saddr), "l"(gaddr), "r"(bytes));
}
__device__ __forceinline__ void cp_commit() {
    asm volatile("cp.async.commit_group;\n");
}
__device__ __forceinline__ void mma_tf32(float c[4], const uint32_t a[4], const uint32_t b[2]) {
    asm volatile(
        "mma.sync.aligned.m16n8k8.row.col.f32.tf32.tf32.f32 "
        "{%0,%1,%2,%3}, {%4,%5,%6,%7}, {%8,%9}, {%0,%1,%2,%3};"
        : "+f"(c[0]), "+f"(c[1]), "+f"(c[2]), "+f"(c[3])
        : "r"(a[0]), "r"(a[1]), "r"(a[2]), "r"(a[3]), "r"(b[0]), "r"(b[1]));
}

// ---------------- small kernels ---------------------------------------------
__global__ void k_init(int totND, int N) {
    int i = blockIdx.x * blockDim.x + threadIdx.x;
    if (i < totND) g_comb[i] = 0.f;
    if (i < N) g_denom[i] = 0.f;
}

__global__ void k_transpose(const float* __restrict__ Wk) {
    __shared__ float t[32][33];
    int bx = blockIdx.x * 32, by = blockIdx.y * 32;
    int tx = threadIdx.x, ty = threadIdx.y;
    #pragma unroll
    for (int i = 0; i < 32; i += 8)
        t[ty + i][tx] = Wk[(by + ty + i) * DIM + bx + tx];
    __syncthreads();
    #pragma unroll
    for (int i = 0; i < 32; i += 8)
        g_wkT[(bx + ty + i) * DIM + by + tx] = t[tx][ty + i];
}

// ---------------- fused edge pass --------------------------------------------
// One warp per edge: score = (x.v[idx] + bq)/16; ex = exp(score) (softmax is
// shift-invariant; scores ~N(0,1) so no max subtraction needed for fp32 safety);
// denom[idx] += ex; comb[idx,:] += ex * x  -- x read ONCE, held in registers.
__global__ __launch_bounds__(256) void k_edge(const float* __restrict__ x,
                                              const int* __restrict__ idx, int E) {
    int warp = threadIdx.x >> 5, lane = threadIdx.x & 31;
    int e = blockIdx.x * 8 + warp;
    if (e >= E) return;
    int n = __ldg(idx + e);
    const float4* xp = (const float4*)(x + (size_t)e * DIM);
    const float4* vp = (const float4*)(g_v + (size_t)n * DIM);
    float4 a0 = xp[lane], a1 = xp[lane + 32];
    float4 b0 = vp[lane], b1 = vp[lane + 32];
    float s = a0.x * b0.x + a0.y * b0.y + a0.z * b0.z + a0.w * b0.w
            + a1.x * b1.x + a1.y * b1.y + a1.z * b1.z + a1.w * b1.w;
    #pragma unroll
    for (int o = 16; o; o >>= 1) s += __shfl_xor_sync(0xffffffffu, s, o);
    float ex = expf((s + g_bq[n]) * 0.0625f);
    if (lane == 0) atomicAdd(&g_denom[n], ex);
    float* cb = g_comb + (size_t)n * DIM;
    red_add_v4(cb + (size_t)lane * 4,        ex * a0.x, ex * a0.y, ex * a0.z, ex * a0.w);
    red_add_v4(cb + (size_t)(lane + 32) * 4, ex * a1.x, ex * a1.y, ex * a1.z, ex * a1.w);
}

// ---------------- tf32 tensor-core GEMM --------------------------------------
// Non-GATE: C = prev @ g_wkT  -> g_v ; blocks with bn==0 also fuse bq = bk.prev
//           (bk passed via the `bg` parameter).
// GATE:     z = comb_unnorm @ Wg[256:512] (phase 1), then scale accumulators by
//           inv[row] = 1/max(denom,1e-9), then += prev @ Wg[0:256] (phase 2);
//           epilogue: sigmoid blend -> out.
#define BM 128
#define BN 128
#define BK 16
#define ASTR 20
#define BSTR 136

template<int KTOT, bool GATE>
__global__ __launch_bounds__(256, 2) void k_gemm_tc(const float* __restrict__ Aprev,
                                                    const float* __restrict__ Bglob,
                                                    const float* __restrict__ bias,
                                                    float* __restrict__ out, int M) {
    __shared__ float As[2][BM * ASTR];
    __shared__ float Bs[2][BK * BSTR];
    __shared__ float bks[DIM];

    // resolve scratch symbol in device code
    const float* B = GATE ? Bglob : (const float*)g_wkT;

    const int tid  = threadIdx.x;
    const int lane = tid & 31;
    const int g    = lane >> 2;
    const int tg   = lane & 3;
    const int wid  = tid >> 5;
    const int wR   = (wid & 3) * 32;
    const int wC   = (wid >> 2) * 64;
    const int bm   = blockIdx.y * BM;
    const int bn   = blockIdx.x * BN;
    const bool do_bq = (!GATE) && (blockIdx.x == 0);

    if (do_bq && tid < 64)
        *(float4*)&bks[tid * 4] = *(const float4*)(bias + tid * 4);

    float inv[2][2];
    if (GATE) {
        #pragma unroll
        for (int mi = 0; mi < 2; mi++)
            #pragma unroll
            for (int half = 0; half < 2; half++) {
                int r = bm + wR + mi * 16 + g + half * 8;
                if (r >= M) r = M - 1;
                inv[mi][half] = 1.f / fmaxf(g_denom[r], 1e-9f);
            }
    }

    float c[2][8][4];
    #pragma unroll
    for (int mi = 0; mi < 2; mi++)
        #pragma unroll
        for (int ni = 0; ni < 8; ni++)
            #pragma unroll
            for (int q = 0; q < 4; q++) c[mi][ni][q] = 0.f;

    // iteration -> (A source, physical k). GATE: comb phase first, prev second.
    auto stage = [&](int buf, int it) {
        int k0;                 // column offset within the A source
        const float* asrc_base; // row-major [.,256] source
        int bkrow;              // physical row base in B
        if (GATE) {
            if (it < 16) { k0 = it * 16;        asrc_base = (const float*)g_comb; bkrow = 256 + k0; }
            else         { k0 = (it - 16) * 16; asrc_base = Aprev;                bkrow = k0; }
        } else {
            k0 = it * 16; asrc_base = Aprev; bkrow = k0;
        }
        #pragma unroll
        for (int j = 0; j < 2; j++) {
            int f    = tid + j * 256;
            int row  = f >> 2;
            int c4   = (f & 3) * 4;
            int grow = bm + row;
            int ok   = grow < M;
            int gr   = ok ? grow : (M - 1);
            const float* src = asrc_base + (size_t)gr * DIM + k0 + c4;
            uint32_t d = (uint32_t)__cvta_generic_to_shared(&As[buf][row * ASTR + c4]);
            cp_async16(d, src, ok ? 16 : 0);
        }
        #pragma unroll
        for (int j = 0; j < 2; j++) {
            int f    = tid + j * 256;
            int krow = f >> 5;
            int c4   = (f & 31) * 4;
            const float* src = B + (size_t)(bkrow + krow) * DIM + bn + c4;
            uint32_t d = (uint32_t)__cvta_generic_to_shared(&Bs[buf][krow * BSTR + c4]);
            cp_async16(d, src, 16);
        }
        cp_commit();
    };

    constexpr int KT = KTOT / BK;
    stage(0, 0);

    float bqacc = 0.f;
    const int bq_row  = tid >> 1;
    const int bq_half = tid & 1;

    #pragma unroll 1
    for (int it = 0; it < KT; it++) {
        if (it + 1 < KT) {
            stage((it + 1) & 1, it + 1);
            asm volatile("cp.async.wait_group 1;\n");
        } else {
            asm volatile("cp.async.wait_group 0;\n");
        }
        __syncthreads();

        const float* Ab = As[it & 1];
        const float* Bb = Bs[it & 1];
        #pragma unroll
        for (int ks = 0; ks < BK; ks += 8) {
            uint32_t a[2][4];
            #pragma unroll
            for (int mi = 0; mi < 2; mi++) {
                int r0 = wR + mi * 16 + g;
                a[mi][0] = __float_as_uint(Ab[(r0)     * ASTR + ks + tg]);
                a[mi][1] = __float_as_uint(Ab[(r0 + 8) * ASTR + ks + tg]);
                a[mi][2] = __float_as_uint(Ab[(r0)     * ASTR + ks + tg + 4]);
                a[mi][3] = __float_as_uint(Ab[(r0 + 8) * ASTR + ks + tg + 4]);
            }
            uint32_t b[8][2];
            #pragma unroll
            for (int ni = 0; ni < 8; ni++) {
                int cc = wC + ni * 8 + g;
                b[ni][0] = __float_as_uint(Bb[(ks + tg)     * BSTR + cc]);
                b[ni][1] = __float_as_uint(Bb[(ks + tg + 4) * BSTR + cc]);
            }
            #pragma unroll
            for (int mi = 0; mi < 2; mi++)
                #pragma unroll
                for (int ni = 0; ni < 8; ni++)
                    mma_tf32(c[mi][ni], a[mi], b[ni]);
        }

        if (do_bq) {
            float s = 0.f;
            #pragma unroll
            for (int j = 0; j < 8; j++)
                s += Ab[bq_row * ASTR + bq_half * 8 + j] * bks[it * 16 + bq_half * 8 + j];
            bqacc += s;
        }

        if (GATE && it == 15) {  // comb phase done: normalize accumulators
            #pragma unroll
            for (int mi = 0; mi < 2; mi++)
                #pragma unroll
                for (int ni = 0; ni < 8; ni++)
                    #pragma unroll
                    for (int q = 0; q < 4; q++)
                        c[mi][ni][q] *= inv[mi][q >> 1];
        }
        __syncthreads();
    }

    if (do_bq) {
        bqacc += __shfl_xor_sync(0xffffffffu, bqacc, 1);
        if (bq_half == 0 && bm + bq_row < M) g_bq[bm + bq_row] = bqacc;
    }

    #pragma unroll
    for (int mi = 0; mi < 2; mi++) {
        #pragma unroll
        for (int half = 0; half < 2; half++) {
            int r = bm + wR + mi * 16 + g + half * 8;
            if (r >= M) continue;
            #pragma unroll
            for (int ni = 0; ni < 8; ni++) {
                int cc = bn + wC + ni * 8 + tg * 2;
                float v0 = c[mi][ni][half * 2 + 0];
                float v1 = c[mi][ni][half * 2 + 1];
                if (GATE) {
                    float2 bgv = *(const float2*)(bias + cc);
                    float2 pv  = *(const float2*)(Aprev + (size_t)r * DIM + cc);
                    float2 cv  = *(const float2*)(g_comb + (size_t)r * DIM + cc);
                    float iv = inv[mi][half];
                    float g0 = 1.f / (1.f + expf(-(v0 + bgv.x)));
                    float g1 = 1.f / (1.f + expf(-(v1 + bgv.y)));
                    float2 o;
                    o.x = g0 * pv.x + (1.f - g0) * (cv.x * iv);
                    o.y = g1 * pv.y + (1.f - g1) * (cv.y * iv);
                    *(float2*)(out + (size_t)r * DIM + cc) = o;
                } else {
                    *(float2*)(g_v + (size_t)r * DIM + cc) = make_float2(v0, v1);
                }
            }
        }
    }
}

// ---------------- launch ------------------------------------------------------
extern "C" void kernel_launch(void* const* d_in, const int* in_sizes, int n_in,
                              void* d_out, int out_size) {
    const float* x    = (const float*)d_in[0];
    const float* prev = (const float*)d_in[1];
    const float* Wk   = (const float*)d_in[2];
    const float* bk   = (const float*)d_in[3];
    const float* Wg   = (const float*)d_in[4];
    const float* bg   = (const float*)d_in[5];
    const int*   idx  = (const int*)d_in[6];
    float* out = (float*)d_out;

    int Dv = in_sizes[3];            // 256
    int E  = in_sizes[0] / Dv;
    int N  = in_sizes[1] / Dv;

    int totND = N * Dv;
    k_init<<<(totND + 255) / 256, 256>>>(totND, N);
    k_transpose<<<dim3(8, 8), dim3(32, 8)>>>(Wk);

    dim3 gg(2, (N + BM - 1) / BM);
    k_gemm_tc<256, false><<<gg, 256>>>(prev, nullptr, bk, nullptr, N);
    k_edge<<<(E + 7) / 8, 256>>>(x, idx, E);
    k_gemm_tc<512, true><<<gg, 256>>>(prev, Wg, bg, out, N);
}

// round 6
// speedup vs baseline: 1.1146x; 1.1146x over previous
#include <cuda_runtime.h>
#include <cuda_bf16.h>
#include <math.h>
#include <stdint.h>

#define DIM   256
#define MAXN  100000
#define MAXE  500000

// ---------------- scratch ---------------------------------------------------
__device__ float g_v[(size_t)MAXN * DIM];     // v[n,:] = W_k @ prev[n,:]
__device__ float g_comb[(size_t)MAXN * DIM];  // unnormalized sum ex * x
__device__ float g_wkT[DIM * DIM];            // W_k transposed
__device__ float g_bq[MAXN];                  // b_k . prev[n]
__device__ float g_denom[MAXN];               // sum ex per node

// ---------------- helpers ---------------------------------------------------
__device__ __forceinline__ void red_add_v4(float* addr, float a, float b, float c, float d) {
    asm volatile("red.global.add.v4.f32 [%0], {%1,%2,%3,%4};"
                 :: "l"(addr), "f"(a), "f"(b), "f"(c), "f"(d) : "memory");
}
__device__ __forceinline__ void cp_async16(uint32_t saddr, const void* gaddr, int bytes) {
    asm volatile("cp.async.ca.shared.global [%0], [%1], 16, %2;\n"
                 :: "r"(saddr), "l"(gaddr), "r"(bytes));
}
__device__ __forceinline__ void cp_commit() {
    asm volatile("cp.async.commit_group;\n");
}
__device__ __forceinline__ void mma_tf32(float c[4], const uint32_t a[4], const uint32_t b[2]) {
    asm volatile(
        "mma.sync.aligned.m16n8k8.row.col.f32.tf32.tf32.f32 "
        "{%0,%1,%2,%3}, {%4,%5,%6,%7}, {%8,%9}, {%0,%1,%2,%3};"
        : "+f"(c[0]), "+f"(c[1]), "+f"(c[2]), "+f"(c[3])
        : "r"(a[0]), "r"(a[1]), "r"(a[2]), "r"(a[3]), "r"(b[0]), "r"(b[1]));
}

__global__ void k_transpose(const float* __restrict__ Wk) {
    __shared__ float t[32][33];
    int bx = blockIdx.x * 32, by = blockIdx.y * 32;
    int tx = threadIdx.x, ty = threadIdx.y;
    #pragma unroll
    for (int i = 0; i < 32; i += 8)
        t[ty + i][tx] = Wk[(by + ty + i) * DIM + bx + tx];
    __syncthreads();
    #pragma unroll
    for (int i = 0; i < 32; i += 8)
        g_wkT[(bx + ty + i) * DIM + by + tx] = t[tx][ty + i];
}

// ---------------- fused edge pass --------------------------------------------
// One warp per edge. x is streamed ONCE with evict-first (__ldcs) so the L2
// stays owned by g_v (gather) and g_comb (scatter RMW) working sets.
__global__ __launch_bounds__(256) void k_edge(const float* __restrict__ x,
                                              const int* __restrict__ idx, int E) {
    int warp = threadIdx.x >> 5, lane = threadIdx.x & 31;
    int e = blockIdx.x * 8 + warp;
    if (e >= E) return;
    int n = __ldg(idx + e);
    const float4* xp = (const float4*)(x + (size_t)e * DIM);
    const float4* vp = (const float4*)(g_v + (size_t)n * DIM);
    float4 a0 = __ldcs(xp + lane);
    float4 a1 = __ldcs(xp + lane + 32);
    float4 b0 = vp[lane], b1 = vp[lane + 32];
    float s = a0.x * b0.x + a0.y * b0.y + a0.z * b0.z + a0.w * b0.w
            + a1.x * b1.x + a1.y * b1.y + a1.z * b1.z + a1.w * b1.w;
    #pragma unroll
    for (int o = 16; o; o >>= 1) s += __shfl_xor_sync(0xffffffffu, s, o);
    float ex = expf((s + g_bq[n]) * 0.0625f);
    if (lane == 0) atomicAdd(&g_denom[n], ex);
    float* cb = g_comb + (size_t)n * DIM;
    red_add_v4(cb + (size_t)lane * 4,        ex * a0.x, ex * a0.y, ex * a0.z, ex * a0.w);
    red_add_v4(cb + (size_t)(lane + 32) * 4, ex * a1.x, ex * a1.y, ex * a1.z, ex * a1.w);
}

// ---------------- tf32 tensor-core GEMM, BM=64 x BN=256 ----------------------
// Non-GATE: C = prev @ g_wkT -> g_v; fused: bq = bk.prev; zero g_comb/g_denom.
// GATE: z = comb @ Wg[256:] first, scale by 1/max(denom,eps), += prev @ Wg[:256];
//       epilogue sigmoid blend -> out.
#define BM 64
#define BN 256
#define BK 16
#define ASTR 20
#define BSTR 264

template<int KTOT, bool GATE>
__global__ __launch_bounds__(256, 2) void k_gemm_tc(const float* __restrict__ Aprev,
                                                    const float* __restrict__ Bglob,
                                                    const float* __restrict__ bias,
                                                    float* __restrict__ out, int M) {
    __shared__ float As[2][BM * ASTR];
    __shared__ float Bs[2][BK * BSTR];
    __shared__ float bks[DIM];

    const float* B = GATE ? Bglob : (const float*)g_wkT;   // device-resolved symbol

    const int tid  = threadIdx.x;
    const int lane = tid & 31;
    const int g    = lane >> 2;
    const int tg   = lane & 3;
    const int wid  = tid >> 5;
    const int wR   = (wid & 1) * 32;    // 2 warp-rows  x 32
    const int wC   = (wid >> 1) * 64;   // 4 warp-cols x 64
    const int bm   = blockIdx.y * BM;

    if (!GATE && tid < 64)
        *(float4*)&bks[tid * 4] = *(const float4*)(bias + tid * 4);

    float inv[2][2];
    if (GATE) {
        #pragma unroll
        for (int mi = 0; mi < 2; mi++)
            #pragma unroll
            for (int half = 0; half < 2; half++) {
                int r = bm + wR + mi * 16 + g + half * 8;
                if (r >= M) r = M - 1;
                inv[mi][half] = 1.f / fmaxf(g_denom[r], 1e-9f);
            }
    }

    float c[2][8][4];
    #pragma unroll
    for (int mi = 0; mi < 2; mi++)
        #pragma unroll
        for (int ni = 0; ni < 8; ni++)
            #pragma unroll
            for (int q = 0; q < 4; q++) c[mi][ni][q] = 0.f;

    auto stage = [&](int buf, int it) {
        int k0; const float* asrc; int bkrow;
        if (GATE) {
            if (it < 16) { k0 = it * 16;        asrc = (const float*)g_comb; bkrow = 256 + k0; }
            else         { k0 = (it - 16) * 16; asrc = Aprev;                bkrow = k0; }
        } else {
            k0 = it * 16; asrc = Aprev; bkrow = k0;
        }
        {   // A: 64 rows x 16 floats = 256 float4, one per thread
            int row  = tid >> 2;
            int c4   = (tid & 3) * 4;
            int grow = bm + row;
            int ok   = grow < M;
            int gr   = ok ? grow : (M - 1);
            const float* src = asrc + (size_t)gr * DIM + k0 + c4;
            uint32_t d = (uint32_t)__cvta_generic_to_shared(&As[buf][row * ASTR + c4]);
            cp_async16(d, src, ok ? 16 : 0);
        }
        #pragma unroll
        for (int j = 0; j < 4; j++) {   // B: 16 rows x 256 floats = 1024 float4
            int f    = tid + j * 256;
            int krow = f >> 6;
            int c4   = (f & 63) * 4;
            const float* src = B + (size_t)(bkrow + krow) * DIM + c4;
            uint32_t d = (uint32_t)__cvta_generic_to_shared(&Bs[buf][krow * BSTR + c4]);
            cp_async16(d, src, 16);
        }
        cp_commit();
    };

    constexpr int KT = KTOT / BK;
    stage(0, 0);

    float bqacc = 0.f;
    const int bq_row = tid >> 2;
    const int bq_q   = tid & 3;

    #pragma unroll 1
    for (int it = 0; it < KT; it++) {
        if (it + 1 < KT) {
            stage((it + 1) & 1, it + 1);
            asm volatile("cp.async.wait_group 1;\n");
        } else {
            asm volatile("cp.async.wait_group 0;\n");
        }
        __syncthreads();

        const float* Ab = As[it & 1];
        const float* Bb = Bs[it & 1];
        #pragma unroll
        for (int ks = 0; ks < BK; ks += 8) {
            uint32_t a[2][4];
            #pragma unroll
            for (int mi = 0; mi < 2; mi++) {
                int r0 = wR + mi * 16 + g;
                a[mi][0] = __float_as_uint(Ab[(r0)     * ASTR + ks + tg]);
                a[mi][1] = __float_as_uint(Ab[(r0 + 8) * ASTR + ks + tg]);
                a[mi][2] = __float_as_uint(Ab[(r0)     * ASTR + ks + tg + 4]);
                a[mi][3] = __float_as_uint(Ab[(r0 + 8) * ASTR + ks + tg + 4]);
            }
            uint32_t b[8][2];
            #pragma unroll
            for (int ni = 0; ni < 8; ni++) {
                int cc = wC + ni * 8 + g;
                b[ni][0] = __float_as_uint(Bb[(ks + tg)     * BSTR + cc]);
                b[ni][1] = __float_as_uint(Bb[(ks + tg + 4) * BSTR + cc]);
            }
            #pragma unroll
            for (int mi = 0; mi < 2; mi++)
                #pragma unroll
                for (int ni = 0; ni < 8; ni++)
                    mma_tf32(c[mi][ni], a[mi], b[ni]);
        }

        if (!GATE) {
            float s = 0.f;
            #pragma unroll
            for (int j = 0; j < 4; j++)
                s += Ab[bq_row * ASTR + bq_q * 4 + j] * bks[it * 16 + bq_q * 4 + j];
            bqacc += s;
        }

        if (GATE && it == 15) {  // comb phase done: normalize accumulators
            #pragma unroll
            for (int mi = 0; mi < 2; mi++)
                #pragma unroll
                for (int ni = 0; ni < 8; ni++)
                    #pragma unroll
                    for (int q = 0; q < 4; q++)
                        c[mi][ni][q] *= inv[mi][q >> 1];
        }
        __syncthreads();
    }

    if (!GATE) {
        bqacc += __shfl_xor_sync(0xffffffffu, bqacc, 1);
        bqacc += __shfl_xor_sync(0xffffffffu, bqacc, 2);
        if (bq_q == 0 && bm + bq_row < M) g_bq[bm + bq_row] = bqacc;
        if (tid < BM && bm + tid < M) g_denom[bm + tid] = 0.f;   // fused init
    }

    #pragma unroll
    for (int mi = 0; mi < 2; mi++) {
        #pragma unroll
        for (int half = 0; half < 2; half++) {
            int r = bm + wR + mi * 16 + g + half * 8;
            if (r >= M) continue;
            #pragma unroll
            for (int ni = 0; ni < 8; ni++) {
                int cc = wC + ni * 8 + tg * 2;
                float v0 = c[mi][ni][half * 2 + 0];
                float v1 = c[mi][ni][half * 2 + 1];
                if (GATE) {
                    float2 bgv = *(const float2*)(bias + cc);
                    float2 pv  = *(const float2*)(Aprev + (size_t)r * DIM + cc);
                    float2 cv  = *(const float2*)(g_comb + (size_t)r * DIM + cc);
                    float iv = inv[mi][half];
                    float g0 = 1.f / (1.f + expf(-(v0 + bgv.x)));
                    float g1 = 1.f / (1.f + expf(-(v1 + bgv.y)));
                    float2 o;
                    o.x = g0 * pv.x + (1.f - g0) * (cv.x * iv);
                    o.y = g1 * pv.y + (1.f - g1) * (cv.y * iv);
                    *(float2*)(out + (size_t)r * DIM + cc) = o;
                } else {
                    *(float2*)(g_v + (size_t)r * DIM + cc) = make_float2(v0, v1);
                    *(float2*)(g_comb + (size_t)r * DIM + cc) = make_float2(0.f, 0.f);  // fused init
                }
            }
        }
    }
}

// ---------------- launch ------------------------------------------------------
extern "C" void kernel_launch(void* const* d_in, const int* in_sizes, int n_in,
                              void* d_out, int out_size) {
    const float* x    = (const float*)d_in[0];
    const float* prev = (const float*)d_in[1];
    const float* Wk   = (const float*)d_in[2];
    const float* bk   = (const float*)d_in[3];
    const float* Wg   = (const float*)d_in[4];
    const float* bg   = (const float*)d_in[5];
    const int*   idx  = (const int*)d_in[6];
    float* out = (float*)d_out;

    int Dv = in_sizes[3];            // 256
    int E  = in_sizes[0] / Dv;
    int N  = in_sizes[1] / Dv;

    k_transpose<<<dim3(8, 8), dim3(32, 8)>>>(Wk);

    dim3 gg(1, (N + BM - 1) / BM);
    k_gemm_tc<256, false><<<gg, 256>>>(prev, nullptr, bk, nullptr, N);
    k_edge<<<(E + 7) / 8, 256>>>(x, idx, E);
    k_gemm_tc<512, true><<<gg, 256>>>(prev, Wg, bg, out, N);
}